// round 9
// baseline (speedup 1.0000x reference)
#include <cuda_runtime.h>
#include <cstdint>
#include <cstddef>

// Problem constants (fixed shapes)
#define B_  32
#define T_  4096
#define H_  256
#define IN_ 128
#define P_  64

// Scratch (t-major [T][B][H]): layer0 pre-activations, h1, h2.
__device__ float g_pre[(size_t)T_ * B_ * H_];
__device__ float g_h1 [(size_t)T_ * B_ * H_];
__device__ float g_h2 [(size_t)T_ * B_ * H_];
__device__ int   g_flag[2 * B_];   // per layer-0 CTA step counters

// ---------------- packed f32x2 helpers (FFMA2: 2 FMAs per issue) ----------------
__device__ __forceinline__ void ffma2(unsigned long long& d, unsigned long long a,
                                      unsigned long long b) {
    asm("fma.rn.f32x2 %0, %1, %2, %0;" : "+l"(d) : "l"(a), "l"(b));
}
__device__ __forceinline__ unsigned long long dup2(float a) {
    unsigned long long r;
    asm("mov.b64 %0, {%1, %1};" : "=l"(r) : "f"(a));
    return r;
}
__device__ __forceinline__ float2 unpack2(unsigned long long v) {
    float2 r;
    asm("mov.b64 {%0, %1}, %2;" : "=f"(r.x), "=f"(r.y) : "l"(v));
    return r;
}

// ---------------------------------------------------------------------------
// Tiled fp32 GEMM:  C[m][n] = act( sum_k A[m][k] * W[n][k] + bias1[n] (+ bias2[n]) )
// Tile: 64(M) x 64(N) x 32(K), 256 threads, 4x4 micro-tile per thread.
// ---------------------------------------------------------------------------
template <bool PERM_IN, bool PERM_OUT, bool SIG>
__global__ void __launch_bounds__(256) gemm_k(
    const float* __restrict__ A, const float* __restrict__ W,
    const float* __restrict__ b1, const float* __restrict__ b2,
    float* __restrict__ C, int K, int N)
{
    __shared__ float AsT[32][68];  // [k][m]
    __shared__ float BsT[32][68];  // [k][n]

    const int tid = threadIdx.x;
    const int tx = tid & 15;
    const int ty = tid >> 4;
    const int m0 = blockIdx.x * 64;
    const int n0 = blockIdx.y * 64;

    unsigned long long acc[4][2];
#pragma unroll
    for (int i = 0; i < 4; ++i) { acc[i][0] = 0ull; acc[i][1] = 0ull; }

    const int r0 = tid >> 3;
    const int q0 = tid & 7;
    const int r1 = r0 + 32;

    long ar0, ar1;
    if (PERM_IN) {
        int ma = m0 + r0, mb = m0 + r1;
        ar0 = (long)(ma & 31) * T_ + (ma >> 5);
        ar1 = (long)(mb & 31) * T_ + (mb >> 5);
    } else {
        ar0 = m0 + r0;
        ar1 = m0 + r1;
    }
    const float* Ap0 = A + ar0 * (long)K + q0 * 4;
    const float* Ap1 = A + ar1 * (long)K + q0 * 4;
    const float* Wp0 = W + (long)(n0 + r0) * K + q0 * 4;
    const float* Wp1 = W + (long)(n0 + r1) * K + q0 * 4;

    for (int kt = 0; kt < K; kt += 32) {
        float4 a0 = *(const float4*)(Ap0 + kt);
        float4 a1 = *(const float4*)(Ap1 + kt);
        float4 w0 = *(const float4*)(Wp0 + kt);
        float4 w1 = *(const float4*)(Wp1 + kt);
        __syncthreads();
        AsT[q0 * 4 + 0][r0] = a0.x; AsT[q0 * 4 + 1][r0] = a0.y;
        AsT[q0 * 4 + 2][r0] = a0.z; AsT[q0 * 4 + 3][r0] = a0.w;
        AsT[q0 * 4 + 0][r1] = a1.x; AsT[q0 * 4 + 1][r1] = a1.y;
        AsT[q0 * 4 + 2][r1] = a1.z; AsT[q0 * 4 + 3][r1] = a1.w;
        BsT[q0 * 4 + 0][r0] = w0.x; BsT[q0 * 4 + 1][r0] = w0.y;
        BsT[q0 * 4 + 2][r0] = w0.z; BsT[q0 * 4 + 3][r0] = w0.w;
        BsT[q0 * 4 + 0][r1] = w1.x; BsT[q0 * 4 + 1][r1] = w1.y;
        BsT[q0 * 4 + 2][r1] = w1.z; BsT[q0 * 4 + 3][r1] = w1.w;
        __syncthreads();

#pragma unroll
        for (int kk = 0; kk < 32; ++kk) {
            float4 a4 = *(const float4*)&AsT[kk][ty * 4];
            ulonglong2 bb = *(const ulonglong2*)&BsT[kk][tx * 4];
            unsigned long long d;
            d = dup2(a4.x); ffma2(acc[0][0], d, bb.x); ffma2(acc[0][1], d, bb.y);
            d = dup2(a4.y); ffma2(acc[1][0], d, bb.x); ffma2(acc[1][1], d, bb.y);
            d = dup2(a4.z); ffma2(acc[2][0], d, bb.x); ffma2(acc[2][1], d, bb.y);
            d = dup2(a4.w); ffma2(acc[3][0], d, bb.x); ffma2(acc[3][1], d, bb.y);
        }
    }

    float4 bv = *(const float4*)&b1[n0 + tx * 4];
    if (b2) {
        float4 b2v = *(const float4*)&b2[n0 + tx * 4];
        bv.x += b2v.x; bv.y += b2v.y; bv.z += b2v.z; bv.w += b2v.w;
    }

#pragma unroll
    for (int i = 0; i < 4; ++i) {
        int m = m0 + ty * 4 + i;
        float2 c01 = unpack2(acc[i][0]);
        float2 c23 = unpack2(acc[i][1]);
        float4 v;
        v.x = c01.x + bv.x; v.y = c01.y + bv.y;
        v.z = c23.x + bv.z; v.w = c23.y + bv.w;
        if (SIG) {
            v.x = 1.f / (1.f + expf(-v.x));
            v.y = 1.f / (1.f + expf(-v.y));
            v.z = 1.f / (1.f + expf(-v.z));
            v.w = 1.f / (1.f + expf(-v.w));
        }
        long orow = PERM_OUT ? ((long)(m & 31) * T_ + (m >> 5)) : (long)m;
        *(float4*)(C + orow * (long)N + n0 + tx * 4) = v;
    }
}

// ---------------------------------------------------------------------------
// Fused pipelined scan: layers 0 and 1 run concurrently, layer 1 one step
// behind. 128 CTAs = 64 clusters of 2 (single wave):
//   blockIdx 0..63   : layer 0, cluster per batch b = blockIdx>>1
//   blockIdx 64..127 : layer 1, cluster per batch b = (blockIdx>>1)&31
// Per cluster, rank r owns outputs [r*128, r*128+128); thread (jl, c=0..3)
// owns k-chunks == c (mod 4) of its W rows, register-resident.
// Layer 0 step (R7-proven): dot(W_hh0, h) + pre0[t], tanh, DSMEM exchange,
// barrier.cluster, then publish flag[2b+rank]=t+1 (threadfence + release).
// Layer 1 step: spin-acquire both flags >= t+1, load h1[t][b] (1KB) to smem,
// dot(W_ih1, x) + dot(W_hh1, h2) + bias, tanh, DSMEM exchange, barrier.
//   -> critical path T+1 steps instead of 2T.
// ---------------------------------------------------------------------------
__global__ void __launch_bounds__(512, 1) __cluster_dims__(2, 1, 1)
fused_scan_k(const float* __restrict__ Whh0, const float* __restrict__ pre0,
             const float* __restrict__ Wih1, const float* __restrict__ Whh1,
             const float* __restrict__ b_ih1, const float* __restrict__ b_hh1,
             float* __restrict__ h1out, float* __restrict__ h2out,
             int* __restrict__ flags)
{
    __shared__ float hbuf[2][H_];
    __shared__ float xbuf[H_];

    const int bx    = blockIdx.x;
    const int layer = bx >> 6;
    const int b     = (bx >> 1) & 31;

    unsigned int rank;
    asm("mov.u32 %0, %%cluster_ctarank;" : "=r"(rank));
    const unsigned int peer = rank ^ 1u;

    const int tid = threadIdx.x;
    const int jl  = tid >> 2;              // local output 0..127
    const int c   = tid & 3;               // k-chunk phase
    const int j   = (int)rank * 128 + jl;  // output index 0..255

    if (tid < H_) hbuf[0][tid] = 0.f;      // h0 = zeros
    __syncthreads();
    asm volatile("barrier.cluster.arrive.aligned;" ::: "memory");
    asm volatile("barrier.cluster.wait.aligned;" ::: "memory");

    // Peer smem address of my h slot.
    unsigned int loc0 = (unsigned int)__cvta_generic_to_shared(&hbuf[0][j]);
    unsigned int rem_h;
    asm("mapa.shared::cluster.u32 %0, %1, %2;" : "=r"(rem_h) : "r"(loc0), "r"(peer));

    if (layer == 0) {
        // ---- layer 0: W_hh0 register-resident (16 ull2 = 32 regs) ----
        ulonglong2 wr[16];
        {
            const float* wrow = Whh0 + (long)j * H_ + c * 4;
#pragma unroll
            for (int i = 0; i < 16; ++i)
                wr[i] = *(const ulonglong2*)(wrow + i * 16);
        }
        const float* preb = pre0 + b * H_ + j;
        float* outb = h1out + b * H_ + j;
        int* flg = flags + 2 * b + (int)rank;

        float pre_cur = (c == 0) ? preb[0] : 0.f;
        int cur = 0;

        for (int t = 0; t < T_; ++t) {
            float pre_next = 0.f;
            if (c == 0 && t + 1 < T_) pre_next = preb[(size_t)(t + 1) * (B_ * H_)];

            const float* h = hbuf[cur] + c * 4;
            unsigned long long a0 = 0ull, a1 = 0ull, a2 = 0ull, a3 = 0ull;
#pragma unroll
            for (int i = 0; i < 16; i += 2) {
                ulonglong2 h2a = *(const ulonglong2*)(h + i * 16);
                ulonglong2 h2b = *(const ulonglong2*)(h + (i + 1) * 16);
                ffma2(a0, h2a.x, wr[i].x);
                ffma2(a1, h2a.y, wr[i].y);
                ffma2(a2, h2b.x, wr[i + 1].x);
                ffma2(a3, h2b.y, wr[i + 1].y);
            }
            float2 s0 = unpack2(a0), s1 = unpack2(a1);
            float2 s2 = unpack2(a2), s3 = unpack2(a3);
            float dot = ((s0.x + s0.y) + (s1.x + s1.y)) +
                        ((s2.x + s2.y) + (s3.x + s3.y));
            dot += __shfl_xor_sync(0xffffffffu, dot, 1);
            dot += __shfl_xor_sync(0xffffffffu, dot, 2);

            const int nxt = cur ^ 1;
            if (c == 0) {
                float v = tanhf(pre_cur + dot);
                hbuf[nxt][j] = v;
                asm volatile("st.shared::cluster.f32 [%0], %1;"
                             :: "r"(rem_h + (unsigned int)(nxt * H_ * 4)), "f"(v)
                             : "memory");
                outb[(size_t)t * (B_ * H_)] = v;
            }
            asm volatile("barrier.cluster.arrive.aligned;" ::: "memory");
            asm volatile("barrier.cluster.wait.aligned;" ::: "memory");
            // Publish h1[t] for this CTA's 128 outputs (all stores above are
            // CTA-wide ordered by the barrier; fence + release-store flag).
            if (tid == 0) {
                __threadfence();
                asm volatile("st.global.release.gpu.s32 [%0], %1;"
                             :: "l"(flg), "r"(t + 1) : "memory");
            }
            cur = nxt;
            pre_cur = pre_next;
        }
    } else {
        // ---- layer 1: W_ih1 + W_hh1 register-resident (32 ull2 = 64 regs) ----
        ulonglong2 wi[16], wh[16];
        {
            const float* wrow = Wih1 + (long)j * H_ + c * 4;
#pragma unroll
            for (int i = 0; i < 16; ++i)
                wi[i] = *(const ulonglong2*)(wrow + i * 16);
        }
        {
            const float* wrow = Whh1 + (long)j * H_ + c * 4;
#pragma unroll
            for (int i = 0; i < 16; ++i)
                wh[i] = *(const ulonglong2*)(wrow + i * 16);
        }
        const float bias = (c == 0) ? (b_ih1[j] + b_hh1[j]) : 0.f;
        const float* xsrc = h1out + b * H_;
        float* outb = h2out + b * H_ + j;
        const int* flg = flags + 2 * b;

        int cur = 0;
        for (int t = 0; t < T_; ++t) {
            // Wait for h1[t][b] (both producer CTAs).
            if (tid < 2) {
                const int* fp = flg + tid;
                int fv;
                do {
                    asm volatile("ld.acquire.gpu.global.s32 %0, [%1];"
                                 : "=r"(fv) : "l"(fp) : "memory");
                } while (fv < t + 1);
            }
            __syncthreads();
            if (tid < H_) xbuf[tid] = xsrc[(size_t)t * (B_ * H_) + tid];
            __syncthreads();

            const float* x = xbuf + c * 4;
            const float* h = hbuf[cur] + c * 4;
            unsigned long long a0 = 0ull, a1 = 0ull, a2 = 0ull, a3 = 0ull;
#pragma unroll
            for (int i = 0; i < 16; ++i) {
                ulonglong2 x2 = *(const ulonglong2*)(x + i * 16);
                ulonglong2 h2 = *(const ulonglong2*)(h + i * 16);
                ffma2(a0, x2.x, wi[i].x);
                ffma2(a1, x2.y, wi[i].y);
                ffma2(a2, h2.x, wh[i].x);
                ffma2(a3, h2.y, wh[i].y);
            }
            float2 s0 = unpack2(a0), s1 = unpack2(a1);
            float2 s2 = unpack2(a2), s3 = unpack2(a3);
            float dot = ((s0.x + s0.y) + (s1.x + s1.y)) +
                        ((s2.x + s2.y) + (s3.x + s3.y));
            dot += __shfl_xor_sync(0xffffffffu, dot, 1);
            dot += __shfl_xor_sync(0xffffffffu, dot, 2);

            const int nxt = cur ^ 1;
            if (c == 0) {
                float v = tanhf(bias + dot);
                hbuf[nxt][j] = v;
                asm volatile("st.shared::cluster.f32 [%0], %1;"
                             :: "r"(rem_h + (unsigned int)(nxt * H_ * 4)), "f"(v)
                             : "memory");
                outb[(size_t)t * (B_ * H_)] = v;
            }
            asm volatile("barrier.cluster.arrive.aligned;" ::: "memory");
            asm volatile("barrier.cluster.wait.aligned;" ::: "memory");
            cur = nxt;
        }
    }

    // Keep cluster co-resident until all remote ops are done.
    asm volatile("barrier.cluster.arrive.aligned;" ::: "memory");
    asm volatile("barrier.cluster.wait.aligned;" ::: "memory");
}

// ---------------------------------------------------------------------------
extern "C" void kernel_launch(void* const* d_in, const int* in_sizes, int n_in,
                              void* d_out, int out_size)
{
    const float* input = (const float*)d_in[0];
    const float* W_ih0 = (const float*)d_in[1];
    const float* W_hh0 = (const float*)d_in[2];
    const float* b_ih0 = (const float*)d_in[3];
    const float* b_hh0 = (const float*)d_in[4];
    const float* W_ih1 = (const float*)d_in[5];
    const float* W_hh1 = (const float*)d_in[6];
    const float* b_ih1 = (const float*)d_in[7];
    const float* b_hh1 = (const float*)d_in[8];
    const float* fc_W  = (const float*)d_in[9];
    const float* fc_b  = (const float*)d_in[10];
    float* out = (float*)d_out;

    float *pre, *h1, *h2;
    int* flags;
    cudaGetSymbolAddress((void**)&pre, g_pre);
    cudaGetSymbolAddress((void**)&h1, g_h1);
    cudaGetSymbolAddress((void**)&h2, g_h2);
    cudaGetSymbolAddress((void**)&flags, g_flag);

    dim3 blk(256);
    dim3 gA((B_ * T_) / 64, H_ / 64);   // 2048 x 4
    dim3 gF((B_ * T_) / 64, P_ / 64);   // 2048 x 1

    // Reset cross-layer flags (graph-capturable, stream-ordered).
    cudaMemsetAsync(flags, 0, 2 * B_ * sizeof(int));
    // Layer 0 input projection: pre0 = x @ W_ih0^T + b_ih0 + b_hh0.
    gemm_k<true, false, false><<<gA, blk>>>(input, W_ih0, b_ih0, b_hh0, pre, IN_, H_);
    // Both recurrences, pipelined (layer 1 trails by one step).
    fused_scan_k<<<4 * B_, 512>>>(W_hh0, pre, W_ih1, W_hh1, b_ih1, b_hh1,
                                  h1, h2, flags);
    // FC head: out[b*T+t][p] = sigmoid(h2 @ fc_W^T + fc_b)
    gemm_k<false, true, true><<<gF, blk>>>(h2, fc_W, fc_b, nullptr, out, H_, P_);
}